// round 2
// baseline (speedup 1.0000x reference)
#include <cuda_runtime.h>
#include <math.h>

// Problem constants (fixed by setup_inputs)
#define NB   32      // batch
#define SH   96      // small h
#define SW   128     // small w
#define BH   768     // big H
#define BW   1024    // big W
#define KS   49      // gaussian taps
#define RAD  24      // (KS-1)/2
#define CHROWS 24    // rows per blur block
#define NCHUNK 4     // SH / CHROWS

// Scratch (device globals; no allocations allowed)
__device__ float g_v[NB * SH * SW];        // small-grid result
__device__ float g_partial[NB * NCHUNK];   // per-chunk sum(exp(v))
__device__ float g_lse[NB];                // per-batch logsumexp (big grid)

// ---------------------------------------------------------------------------
// Fused separable Gaussian blur + centerbias + priority + partial sum(exp)
// grid = NB*NCHUNK blocks, 256 threads. Block (b, c) computes rows
// [c*24, c*24+24) of the 96x128 small image for batch b.
// ---------------------------------------------------------------------------
__global__ void __launch_bounds__(256) blur_kernel(
    const float* __restrict__ readout,     // NB*1*SH*SW
    const float* __restrict__ centerbias,  // NB*BH*BW
    const float* __restrict__ scaling,     // NB
    const int*   __restrict__ dsidx,       // NB
    const float* __restrict__ ds_sigma,    // nd
    const float* __restrict__ ds_cbw,      // nd
    const float* __restrict__ ds_prio,     // nd
    int nd)
{
    __shared__ float in_s[(CHROWS + 2 * RAD) * SW];  // 72*128 floats = 36 KB
    __shared__ float w_s[KS];
    __shared__ float red_s[8];
    __shared__ float s_prio, s_cbw;

    const int bx  = blockIdx.x;
    const int b   = bx >> 2;
    const int c   = bx & 3;
    const int r0  = c * CHROWS;
    const int tid = threadIdx.x;

    // --- per-batch gaussian weights + scalars ---
    if (tid < KS) {
        int   di    = dsidx[b];
        float sigma = ds_sigma[di] * scaling[b];
        float t     = ((float)tid - (float)RAD) / sigma;
        w_s[tid]    = expf(-0.5f * t * t);
    }
    if (tid == 64) {
        int   di = dsidx[b];
        float m  = 0.f;
        for (int i = 0; i < nd; i++) m += ds_prio[i];
        m /= (float)nd;
        s_prio = expf(ds_prio[di] - m);
        s_cbw  = ds_cbw[di];
    }
    __syncthreads();
    if (tid == 0) {
        float s = 0.f;
        for (int k = 0; k < KS; k++) s += w_s[k];
        float inv = 1.f / s;
        for (int k = 0; k < KS; k++) w_s[k] *= inv;
    }
    __syncthreads();

    // --- load input tile (72 rows with edge clamp) ---
    const float* rin = readout + b * SH * SW;
    for (int i = tid; i < (CHROWS + 2 * RAD) * SW; i += 256) {
        int j  = i >> 7;        // tile row
        int x  = i & 127;       // col
        int gr = r0 - RAD + j;
        gr = min(max(gr, 0), SH - 1);
        in_s[j * SW + x] = rin[gr * SW + x];
    }
    __syncthreads();

    const int x      = tid & 127;   // column owned by this thread
    const int g      = tid >> 7;    // 0 or 1 (row half)
    const int lrbase = g * 12;      // local output row base (12 rows/thread)

    // --- vertical pass: acc[o] = sum_k w[k] * in[lrbase+o+k][x] ---
    float acc[12];
#pragma unroll
    for (int o = 0; o < 12; o++) acc[o] = 0.f;

    const float* inp = in_s + lrbase * SW + x;
#pragma unroll 1
    for (int k = 0; k < KS; k++) {
        float wk = w_s[k];
#pragma unroll
        for (int o = 0; o < 12; o++)
            acc[o] += wk * inp[o * SW];
        inp += SW;
    }

    // mid buffer aliases the (now dead) input tile
    __syncthreads();
    float* mid_s = in_s;  // CHROWS x SW
#pragma unroll
    for (int o = 0; o < 12; o++) mid_s[(lrbase + o) * SW + x] = acc[o];
    __syncthreads();

    // --- horizontal pass with edge clamp ---
#pragma unroll
    for (int o = 0; o < 12; o++) acc[o] = 0.f;
#pragma unroll 1
    for (int k = 0; k < KS; k++) {
        float wk = w_s[k];
        int xx = x + k - RAD;
        xx = min(max(xx, 0), SW - 1);
        const float* mp = mid_s + lrbase * SW + xx;
#pragma unroll
        for (int o = 0; o < 12; o++)
            acc[o] += wk * mp[o * SW];
    }

    // --- priority scale, centerbias add, store v, accumulate exp ---
    const float* cb = centerbias + (size_t)b * BH * BW;
    float esum = 0.f;
    float prio = s_prio, cbw = s_cbw;
#pragma unroll
    for (int o = 0; o < 12; o++) {
        int r = r0 + lrbase + o;
        float val = acc[o] * prio + cbw * cb[(r * 8) * BW + x * 8];
        g_v[(b * SH + r) * SW + x] = val;
        esum += expf(val);
    }

    // --- deterministic block reduce of esum ---
#pragma unroll
    for (int off = 16; off > 0; off >>= 1)
        esum += __shfl_down_sync(0xffffffffu, esum, off);
    if ((tid & 31) == 0) red_s[tid >> 5] = esum;
    __syncthreads();
    if (tid < 8) {
        float v = red_s[tid];
#pragma unroll
        for (int off = 4; off > 0; off >>= 1)
            v += __shfl_down_sync(0x000000ffu, v, off);
        if (tid == 0) g_partial[bx] = v;
    }
}

// ---------------------------------------------------------------------------
// Per-batch LSE: lse_big = log(sum of chunk partials) + log(64)
// (upsample is exact 8x8 replication -> LSE over big grid = LSE_small + ln 64)
// ---------------------------------------------------------------------------
__global__ void lse_kernel()
{
    int b = threadIdx.x;
    if (b < NB) {
        float s = g_partial[b * 4 + 0] + g_partial[b * 4 + 1]
                + g_partial[b * 4 + 2] + g_partial[b * 4 + 3];
        g_lse[b] = logf(s) + 4.1588830833596718565f;  // ln(64)
    }
}

// ---------------------------------------------------------------------------
// Broadcast-write: out[b,y,x] = v[b, y>>3, x>>3] - lse[b], float4 stores.
// Each aligned float4 lies inside one 8-wide nearest cell.
// ---------------------------------------------------------------------------
__global__ void __launch_bounds__(256) out_kernel(float4* __restrict__ out)
{
    const int N4 = NB * BH * BW / 4;            // 6291456
    int stride = gridDim.x * blockDim.x;
    for (int i = blockIdx.x * blockDim.x + threadIdx.x; i < N4; i += stride) {
        int flat = i << 2;
        int b    = flat / (BH * BW);
        int rem  = flat - b * (BH * BW);
        int y    = rem >> 10;
        int xq   = rem & 1023;
        float vv = g_v[(b * SH + (y >> 3)) * SW + (xq >> 3)];
        float o  = vv - g_lse[b];
        out[i] = make_float4(o, o, o, o);
    }
}

// ---------------------------------------------------------------------------
extern "C" void kernel_launch(void* const* d_in, const int* in_sizes, int n_in,
                              void* d_out, int out_size)
{
    const float* readout    = (const float*)d_in[0];
    const float* centerbias = (const float*)d_in[1];
    const float* scaling    = (const float*)d_in[2];
    const int*   dsidx      = (const int*)  d_in[3];
    const float* ds_sigma   = (const float*)d_in[4];
    const float* ds_cbw     = (const float*)d_in[5];
    const float* ds_prio    = (const float*)d_in[6];
    int nd = in_sizes[4];

    blur_kernel<<<NB * NCHUNK, 256>>>(readout, centerbias, scaling, dsidx,
                                      ds_sigma, ds_cbw, ds_prio, nd);
    lse_kernel<<<1, 32>>>();
    out_kernel<<<6144, 256>>>((float4*)d_out);
}

// round 4
// speedup vs baseline: 1.2772x; 1.2772x over previous
#include <cuda_runtime.h>
#include <math.h>

// Problem constants (fixed by setup_inputs)
#define NB   32      // batch
#define SH   96      // small h
#define SW   128     // small w
#define BH   768     // big H
#define BW   1024    // big W
#define KS   49      // gaussian taps
#define RAD  24      // (KS-1)/2
#define CHROWS 24    // rows per blur block
#define NCHUNK 4     // SH / CHROWS
#define LN64 4.1588830833596718565f

// Scratch (device globals; no allocations allowed)
__device__ float g_v[NB * SH * SW];        // small-grid result
__device__ float g_partial[NB * NCHUNK];   // per-chunk sum(exp(v))

// ---------------------------------------------------------------------------
// Fused separable Gaussian blur + centerbias + priority + partial sum(exp)
// grid = NB*NCHUNK blocks, 256 threads. Block (b, c) computes rows
// [c*24, c*24+24) of the 96x128 small image for batch b.
// ---------------------------------------------------------------------------
__global__ void __launch_bounds__(256) blur_kernel(
    const float* __restrict__ readout,     // NB*1*SH*SW
    const float* __restrict__ centerbias,  // NB*BH*BW
    const float* __restrict__ scaling,     // NB
    const int*   __restrict__ dsidx,       // NB
    const float* __restrict__ ds_sigma,    // nd
    const float* __restrict__ ds_cbw,      // nd
    const float* __restrict__ ds_prio,     // nd
    int nd)
{
    __shared__ float in_s[(CHROWS + 2 * RAD) * SW];  // 72*128 floats = 36 KB
    __shared__ float w_s[KS];
    __shared__ float red_s[8];
    __shared__ float s_prio, s_cbw;

    const int bx  = blockIdx.x;
    const int b   = bx >> 2;
    const int c   = bx & 3;
    const int r0  = c * CHROWS;
    const int tid = threadIdx.x;

    // --- per-batch gaussian weights + scalars ---
    if (tid < KS) {
        int   di    = dsidx[b];
        float sigma = ds_sigma[di] * scaling[b];
        float t     = ((float)tid - (float)RAD) / sigma;
        w_s[tid]    = expf(-0.5f * t * t);
    }
    if (tid == 64) {
        int   di = dsidx[b];
        float m  = 0.f;
        for (int i = 0; i < nd; i++) m += ds_prio[i];
        m /= (float)nd;
        s_prio = expf(ds_prio[di] - m);
        s_cbw  = ds_cbw[di];
    }
    __syncthreads();
    if (tid == 0) {
        float s = 0.f;
        for (int k = 0; k < KS; k++) s += w_s[k];
        float inv = 1.f / s;
        for (int k = 0; k < KS; k++) w_s[k] *= inv;
    }
    __syncthreads();

    // --- load input tile (72 rows with edge clamp) ---
    const float* rin = readout + b * SH * SW;
    for (int i = tid; i < (CHROWS + 2 * RAD) * SW; i += 256) {
        int j  = i >> 7;        // tile row
        int x  = i & 127;       // col
        int gr = r0 - RAD + j;
        gr = min(max(gr, 0), SH - 1);
        in_s[j * SW + x] = rin[gr * SW + x];
    }
    __syncthreads();

    const int x      = tid & 127;   // column owned by this thread
    const int g      = tid >> 7;    // 0 or 1 (row half)
    const int lrbase = g * 12;      // local output row base (12 rows/thread)

    // --- vertical pass, 12-register sliding window over input rows ---
    // acc[o] = sum_k w[k] * in[lrbase+o+k][x]; window slot (k+o)%12 = row k+o.
    float acc[12];
#pragma unroll
    for (int o = 0; o < 12; o++) acc[o] = 0.f;

    const float* colp = in_s + x;
    float win[12];
#pragma unroll
    for (int j = 0; j < 11; j++)
        win[j] = colp[(lrbase + j) * SW];

#pragma unroll
    for (int k = 0; k < KS; k++) {
        win[(k + 11) % 12] = colp[(lrbase + k + 11) * SW];
        float wk = w_s[k];
#pragma unroll
        for (int o = 0; o < 12; o++)
            acc[o] += wk * win[(k + o) % 12];
    }

    // mid buffer aliases the (now dead) input tile
    __syncthreads();
    float* mid_s = in_s;  // CHROWS x SW
#pragma unroll
    for (int o = 0; o < 12; o++) mid_s[(lrbase + o) * SW + x] = acc[o];
    __syncthreads();

    // --- horizontal pass with edge clamp ---
#pragma unroll
    for (int o = 0; o < 12; o++) acc[o] = 0.f;
#pragma unroll 1
    for (int k = 0; k < KS; k++) {
        float wk = w_s[k];
        int xx = x + k - RAD;
        xx = min(max(xx, 0), SW - 1);
        const float* mp = mid_s + lrbase * SW + xx;
#pragma unroll
        for (int o = 0; o < 12; o++)
            acc[o] += wk * mp[o * SW];
    }

    // --- priority scale, centerbias add, store v, accumulate exp ---
    const float* cb = centerbias + (size_t)b * BH * BW;
    float esum = 0.f;
    float prio = s_prio, cbw = s_cbw;
#pragma unroll
    for (int o = 0; o < 12; o++) {
        int r = r0 + lrbase + o;
        float val = acc[o] * prio + cbw * cb[(r * 8) * BW + x * 8];
        g_v[(b * SH + r) * SW + x] = val;
        esum += expf(val);
    }

    // --- deterministic block reduce of esum ---
#pragma unroll
    for (int off = 16; off > 0; off >>= 1)
        esum += __shfl_down_sync(0xffffffffu, esum, off);
    if ((tid & 31) == 0) red_s[tid >> 5] = esum;
    __syncthreads();
    if (tid < 8) {
        float v = red_s[tid];
#pragma unroll
        for (int off = 4; off > 0; off >>= 1)
            v += __shfl_down_sync(0x000000ffu, v, off);
        if (tid == 0) g_partial[bx] = v;
    }
}

// ---------------------------------------------------------------------------
// Broadcast-write with inline LSE. Block = (b, small row r): writes big rows
// [8r, 8r+8) of batch b. Thread tid owns float4 #tid of each big row; its 4
// floats all map to small cell tid>>1. 8 coalesced STG.128 per thread, with
// streaming hint (no reuse). lse[b] computed redundantly per thread from the
// 4 chunk partials (exact upsample replication => LSE_big = LSE_small+ln 64).
// ---------------------------------------------------------------------------
__global__ void __launch_bounds__(256) out_kernel(float4* __restrict__ out)
{
    const int blk = blockIdx.x;          // 0 .. NB*SH-1
    const int b   = blk / SH;
    const int r   = blk - b * SH;
    const int tid = threadIdx.x;

    float s = g_partial[b * 4 + 0] + g_partial[b * 4 + 1]
            + g_partial[b * 4 + 2] + g_partial[b * 4 + 3];
    float lse = logf(s) + LN64;

    float vv = __ldg(g_v + (b * SH + r) * SW + (tid >> 1)) - lse;
    float4 val = make_float4(vv, vv, vv, vv);

    float4* obase = out + ((size_t)b * BH + (size_t)r * 8) * (BW / 4) + tid;
#pragma unroll
    for (int j = 0; j < 8; j++)
        __stcs(obase + j * (BW / 4), val);
}

// ---------------------------------------------------------------------------
extern "C" void kernel_launch(void* const* d_in, const int* in_sizes, int n_in,
                              void* d_out, int out_size)
{
    const float* readout    = (const float*)d_in[0];
    const float* centerbias = (const float*)d_in[1];
    const float* scaling    = (const float*)d_in[2];
    const int*   dsidx      = (const int*)  d_in[3];
    const float* ds_sigma   = (const float*)d_in[4];
    const float* ds_cbw     = (const float*)d_in[5];
    const float* ds_prio    = (const float*)d_in[6];
    int nd = in_sizes[4];

    blur_kernel<<<NB * NCHUNK, 256>>>(readout, centerbias, scaling, dsidx,
                                      ds_sigma, ds_cbw, ds_prio, nd);
    out_kernel<<<NB * SH, 256>>>((float4*)d_out);
}